// round 10
// baseline (speedup 1.0000x reference)
#include <cuda_runtime.h>
#include <cuda_bf16.h>
#include <cstddef>

// Problem shape (fixed per reference): feats [B, C, H, W] fp32, R [H, C, C] fp32.
#define Bn 16
#define Cn 256
#define Hn 128
#define Wn 128
#define Kn (Cn / 2)   // 128 channel pairs

// Fused streaming rotation, 2 row-tiles per thread for deeper MLP.
// One thread = (b, k, {h, h+64}, w4):
//   4 independent LDG.128 front-batched (MLP_p1=4), 4 STG.128.
// Low 5 bits = w4 -> each warp streams one contiguous 128-float row
// (fully coalesced); (b, k, h) warp-uniform -> cos/sin loads broadcast.
// feats/out have zero reuse -> streaming hints keep the R-diagonal lines in L2.
__global__ void __launch_bounds__(256) rope_rotate_fused2_kernel(
    const float* __restrict__ f,
    const float* __restrict__ R,
    float* __restrict__ out) {
    unsigned tid = blockIdx.x * blockDim.x + threadIdx.x;
    unsigned w4 = tid & 31u;            // W/4 = 32
    unsigned h  = (tid >> 5) & 63u;     // lower half of H; pair with h+64
    unsigned k  = (tid >> 11) & 127u;   // Kn
    unsigned b  = tid >> 18;            // Bn

    // Warp-uniform 2x2 block extraction from the dense rotation matrix:
    //   cos = R[h, 2k, 2k],  sin = R[h, 2k+1, 2k]
    const float* Rh0 = R + (size_t)h * (Cn * Cn) + (size_t)(2u * k) * Cn + 2u * k;
    const float* Rh1 = Rh0 + (size_t)64 * (Cn * Cn);
    float c0 = __ldg(Rh0);
    float s0 = __ldg(Rh0 + Cn);
    float c1 = __ldg(Rh1);
    float s1 = __ldg(Rh1 + Cn);

    size_t base0 = ((((size_t)b * Cn + 2u * k) * Hn + h) * Wn) + 4u * w4;
    size_t base1 = base0 + (size_t)64 * Wn;           // h+64
    const size_t chan = (size_t)Hn * Wn;              // odd-channel offset

    // Front-batch all 4 independent 128-bit loads.
    const float4 e0 = __ldcs(reinterpret_cast<const float4*>(f + base0));
    const float4 o0 = __ldcs(reinterpret_cast<const float4*>(f + base0 + chan));
    const float4 e1 = __ldcs(reinterpret_cast<const float4*>(f + base1));
    const float4 o1 = __ldcs(reinterpret_cast<const float4*>(f + base1 + chan));

    float4 re0, ro0, re1, ro1;
    re0.x = c0 * e0.x - s0 * o0.x;  ro0.x = s0 * e0.x + c0 * o0.x;
    re0.y = c0 * e0.y - s0 * o0.y;  ro0.y = s0 * e0.y + c0 * o0.y;
    re0.z = c0 * e0.z - s0 * o0.z;  ro0.z = s0 * e0.z + c0 * o0.z;
    re0.w = c0 * e0.w - s0 * o0.w;  ro0.w = s0 * e0.w + c0 * o0.w;

    re1.x = c1 * e1.x - s1 * o1.x;  ro1.x = s1 * e1.x + c1 * o1.x;
    re1.y = c1 * e1.y - s1 * o1.y;  ro1.y = s1 * e1.y + c1 * o1.y;
    re1.z = c1 * e1.z - s1 * o1.z;  ro1.z = s1 * e1.z + c1 * o1.z;
    re1.w = c1 * e1.w - s1 * o1.w;  ro1.w = s1 * e1.w + c1 * o1.w;

    __stcs(reinterpret_cast<float4*>(out + base0), re0);
    __stcs(reinterpret_cast<float4*>(out + base0 + chan), ro0);
    __stcs(reinterpret_cast<float4*>(out + base1), re1);
    __stcs(reinterpret_cast<float4*>(out + base1 + chan), ro1);
}

extern "C" void kernel_launch(void* const* d_in, const int* in_sizes, int n_in,
                              void* d_out, int out_size) {
    const float* feats = (const float*)d_in[0];   // [16, 256, 128, 128]
    const float* rota  = (const float*)d_in[1];   // [128, 256, 256]
    float* out = (float*)d_out;                   // [16, 256, 128, 128]
    (void)in_sizes; (void)n_in; (void)out_size;

    // Single fused launch: Bn*Kn*(Hn/2)*(Wn/4) = 8,388,608 threads.
    const unsigned total = Bn * Kn * (Hn / 2) * (Wn / 4);
    rope_rotate_fused2_kernel<<<total / 256, 256>>>(feats, rota, out);
}